// round 4
// baseline (speedup 1.0000x reference)
#include <cuda_runtime.h>
#include <cuda_bf16.h>

// Problem: SpatialConsistencyLoss
//   original, enhanced: [32,3,512,512] f32
//   p = avg_pool4(mean_c(orig)) - avg_pool4(mean_c(enh))   [32,128,128]
//   loss[i,j] = sum over 4 dirs of (p[i,j] - p[nbr])^2, zero-padded
// Output: [32,1,128,128] f32 (524288 elems)

#define B 32
#define HP 128           // pooled H
#define WP 128           // pooled W
#define NPOOL (B * HP * WP)   // 524288
#define HIN 512
#define WIN 512
#define CH_STRIDE (HIN * WIN)          // 262144
#define IMG_STRIDE (3 * CH_STRIDE)     // 786432

// Scratch for the pooled difference field (2 MB). Device globals are the
// sanctioned alloc-free scratch mechanism.
__device__ float g_pooled[NPOOL];

__global__ void pool_diff_kernel(const float* __restrict__ orig,
                                 const float* __restrict__ enh) {
    int idx = blockIdx.x * blockDim.x + threadIdx.x;
    if (idx >= NPOOL) return;

    int j = idx & (WP - 1);
    int i = (idx >> 7) & (HP - 1);
    int b = idx >> 14;

    // Base offset of the 4x4 input block for channel 0
    int base0 = b * IMG_STRIDE + (i * 4) * WIN + (j * 4);

    float s = 0.0f;
#pragma unroll
    for (int c = 0; c < 3; ++c) {
        int base = base0 + c * CH_STRIDE;
#pragma unroll
        for (int r = 0; r < 4; ++r) {
            float4 ov = *reinterpret_cast<const float4*>(orig + base + r * WIN);
            float4 ev = *reinterpret_cast<const float4*>(enh  + base + r * WIN);
            s += (ov.x - ev.x) + (ov.y - ev.y) + (ov.z - ev.z) + (ov.w - ev.w);
        }
    }
    g_pooled[idx] = s * (1.0f / 48.0f);   // /3 channels, /16 pool
}

__device__ __forceinline__ float sq(float x) { return x * x; }

// One thread = 4 adjacent output pixels (one float4 along j).
// Loads: center float4, up float4, down float4, left scalar, right scalar.
__global__ void loss_kernel_v4(float* __restrict__ out) {
    int t = blockIdx.x * blockDim.x + threadIdx.x;   // 0 .. NPOOL/4 - 1
    if (t >= NPOOL / 4) return;

    int j4  = (t & 31) << 2;      // 0,4,...,124 : first j of the quad
    int row = t >> 5;             // b*128 + i, 0..4095
    int i   = row & (HP - 1);
    int base = (row << 7) + j4;   // scalar index of first element

    const float4* p4 = reinterpret_cast<const float4*>(g_pooled);
    float4 c  = p4[base >> 2];
    float4 up = (i > 0)      ? p4[(base - WP) >> 2] : make_float4(0.f, 0.f, 0.f, 0.f);
    float4 dn = (i < HP - 1) ? p4[(base + WP) >> 2] : make_float4(0.f, 0.f, 0.f, 0.f);
    float left  = (j4 > 0)       ? g_pooled[base - 1] : 0.f;
    float right = (j4 < WP - 4)  ? g_pooled[base + 4] : 0.f;

    float4 o;
    o.x = sq(c.x - left) + sq(c.x - c.y)   + sq(c.x - up.x) + sq(c.x - dn.x);
    o.y = sq(c.y - c.x)  + sq(c.y - c.z)   + sq(c.y - up.y) + sq(c.y - dn.y);
    o.z = sq(c.z - c.y)  + sq(c.z - c.w)   + sq(c.z - up.z) + sq(c.z - dn.z);
    o.w = sq(c.w - c.z)  + sq(c.w - right) + sq(c.w - up.w) + sq(c.w - dn.w);

    reinterpret_cast<float4*>(out)[base >> 2] = o;
}

extern "C" void kernel_launch(void* const* d_in, const int* in_sizes, int n_in,
                              void* d_out, int out_size) {
    const float* orig = (const float*)d_in[0];
    const float* enh  = (const float*)d_in[1];
    float* out = (float*)d_out;

    const int threads = 256;

    pool_diff_kernel<<<(NPOOL + threads - 1) / threads, threads>>>(orig, enh);
    loss_kernel_v4<<<(NPOOL / 4 + threads - 1) / threads, threads>>>(out);
}